// round 1
// baseline (speedup 1.0000x reference)
#include <cuda_runtime.h>
#include <math.h>

#define NTOK 16384
#define DIM  1024
#define NE   8
#define CAP  2560   // int(1.25 * 16384 / 8)

#define BM 128
#define BN 128
#define BK 16

// ---------------- scratch (__device__ globals: no allocation allowed) ------
__device__ int   g_top[NTOK * 2];         // top-2 expert ids per token
__device__ float g_gate[NTOK * 2];        // softmax gates per token
__device__ int   g_row_token[NE * CAP];   // token id per expert slot
__device__ float g_row_gate[NE * CAP];    // gate per expert slot
__device__ int   g_load[NE];              // valid rows per expert
__device__ float g_H[(size_t)NE * CAP * DIM];  // hidden activations (84 MB)

// ---------------- router: logits = x @ Wr^T + br; top-2 + softmax ---------
__global__ void router_kernel(const float* __restrict__ x,
                              const float* __restrict__ Wr,
                              const float* __restrict__ br) {
    int token = (blockIdx.x * blockDim.x + threadIdx.x) >> 5;
    int lane  = threadIdx.x & 31;
    if (token >= NTOK) return;
    const float* xr = x + (size_t)token * DIM;

    float acc[NE];
#pragma unroll
    for (int e = 0; e < NE; e++) acc[e] = 0.f;

    for (int d = lane; d < DIM; d += 32) {
        float xv = xr[d];
#pragma unroll
        for (int e = 0; e < NE; e++) acc[e] += xv * Wr[e * DIM + d];
    }
#pragma unroll
    for (int e = 0; e < NE; e++) {
#pragma unroll
        for (int o = 16; o; o >>= 1)
            acc[e] += __shfl_xor_sync(0xffffffffu, acc[e], o);
    }
    if (lane == 0) {
        float l[NE];
#pragma unroll
        for (int e = 0; e < NE; e++) l[e] = acc[e] + br[e];
        // top-1 (ties -> lowest index, matching jax.lax.top_k)
        float v1 = -3.4e38f; int i1 = 0;
#pragma unroll
        for (int e = 0; e < NE; e++) if (l[e] > v1) { v1 = l[e]; i1 = e; }
        float v2 = -3.4e38f; int i2 = 0;
#pragma unroll
        for (int e = 0; e < NE; e++) if (e != i1 && l[e] > v2) { v2 = l[e]; i2 = e; }
        float ex = expf(v2 - v1);           // v2 <= v1 -> safe
        float inv = 1.f / (1.f + ex);
        g_top[2 * token]     = i1;
        g_top[2 * token + 1] = i2;
        g_gate[2 * token]     = inv;
        g_gate[2 * token + 1] = ex * inv;
    }
}

// ---------------- dispatch scan: stable, token-order slot assignment ------
__global__ void scan_kernel() {
    int e = blockIdx.x;
    __shared__ int wsum[32];
    __shared__ int total_s;
    int lane = threadIdx.x & 31;
    int wid  = threadIdx.x >> 5;
    int running = 0;
    for (int base = 0; base < NTOK; base += 1024) {
        int n = base + threadIdx.x;
        int k = -1;
        int t0 = g_top[2 * n], t1 = g_top[2 * n + 1];
        if (t0 == e) k = 0; else if (t1 == e) k = 1;
        unsigned b = __ballot_sync(0xffffffffu, k >= 0);
        int pw = __popc(b & ((1u << lane) - 1u));
        if (lane == 0) wsum[wid] = __popc(b);
        __syncthreads();
        if (wid == 0) {
            int v = wsum[lane];
            int s = v;
#pragma unroll
            for (int o = 1; o < 32; o <<= 1) {
                int u = __shfl_up_sync(0xffffffffu, s, o);
                if (lane >= o) s += u;
            }
            wsum[lane] = s - v;          // exclusive
            if (lane == 31) total_s = s;
        }
        __syncthreads();
        if (k >= 0) {
            int pos = running + wsum[wid] + pw;
            if (pos < CAP) {
                g_row_token[e * CAP + pos] = n;
                g_row_gate[e * CAP + pos]  = g_gate[2 * n + k];
            }
        }
        running += total_s;
        __syncthreads();
    }
    if (threadIdx.x == 0) g_load[e] = running < CAP ? running : CAP;
}

// ---------------- GEMM1: H = relu( gather(x) @ W1[e]^T + b1[e] ) ----------
__global__ __launch_bounds__(256, 2)
void gemm1_kernel(const float* __restrict__ x,
                  const float* __restrict__ W1,
                  const float* __restrict__ b1) {
    __shared__ float As[BK][BM + 4];
    __shared__ float Bs[BK][BN + 4];
    __shared__ int   rows[BM];

    int e  = blockIdx.z;
    int loadE = g_load[e];
    int m0 = blockIdx.y * BM;
    int n0 = blockIdx.x * BN;
    if (m0 >= loadE) return;
    int tid = threadIdx.x;
    int tx = tid & 15, ty = tid >> 4;

    if (tid < BM) {
        int m = m0 + tid;
        rows[tid] = (m < loadE) ? g_row_token[e * CAP + tid + m0] : 0;
    }
    __syncthreads();

    const float* W = W1 + (size_t)e * DIM * DIM;
    int sr = tid >> 1;
    int sk = (tid & 1) << 3;
    const float* pa = x + (size_t)rows[sr] * DIM + sk;
    const float* pb = W + (size_t)(n0 + sr) * DIM + sk;

    float acc[8][8];
#pragma unroll
    for (int i = 0; i < 8; i++)
#pragma unroll
        for (int j = 0; j < 8; j++) acc[i][j] = 0.f;

#pragma unroll 1
    for (int k0 = 0; k0 < DIM; k0 += BK) {
        float4 av0 = *(const float4*)(pa + k0);
        float4 av1 = *(const float4*)(pa + k0 + 4);
        float4 bv0 = *(const float4*)(pb + k0);
        float4 bv1 = *(const float4*)(pb + k0 + 4);
        __syncthreads();
        As[sk + 0][sr] = av0.x; As[sk + 1][sr] = av0.y;
        As[sk + 2][sr] = av0.z; As[sk + 3][sr] = av0.w;
        As[sk + 4][sr] = av1.x; As[sk + 5][sr] = av1.y;
        As[sk + 6][sr] = av1.z; As[sk + 7][sr] = av1.w;
        Bs[sk + 0][sr] = bv0.x; Bs[sk + 1][sr] = bv0.y;
        Bs[sk + 2][sr] = bv0.z; Bs[sk + 3][sr] = bv0.w;
        Bs[sk + 4][sr] = bv1.x; Bs[sk + 5][sr] = bv1.y;
        Bs[sk + 6][sr] = bv1.z; Bs[sk + 7][sr] = bv1.w;
        __syncthreads();
#pragma unroll
        for (int kk = 0; kk < BK; kk++) {
            float a[8], b[8];
            *(float4*)(a)     = *(const float4*)&As[kk][ty * 4];
            *(float4*)(a + 4) = *(const float4*)&As[kk][64 + ty * 4];
            *(float4*)(b)     = *(const float4*)&Bs[kk][tx * 4];
            *(float4*)(b + 4) = *(const float4*)&Bs[kk][64 + tx * 4];
#pragma unroll
            for (int i = 0; i < 8; i++)
#pragma unroll
                for (int j = 0; j < 8; j++) acc[i][j] += a[i] * b[j];
        }
    }

    float b1v[8];
#pragma unroll
    for (int j = 0; j < 8; j++) {
        int c = (j < 4) ? tx * 4 + j : 64 + tx * 4 + j - 4;
        b1v[j] = b1[e * DIM + n0 + c];
    }
#pragma unroll
    for (int i = 0; i < 8; i++) {
        int m = m0 + ((i < 4) ? ty * 4 + i : 64 + ty * 4 + i - 4);
        float* hp = g_H + ((size_t)e * CAP + m) * DIM + n0;
#pragma unroll
        for (int j = 0; j < 8; j++) {
            int c = (j < 4) ? tx * 4 + j : 64 + tx * 4 + j - 4;
            float v = acc[i][j] + b1v[j];
            hp[c] = v > 0.f ? v : 0.f;
        }
    }
}

// ---------------- GEMM2: out += gate * ( H @ W2[e]^T + b2[e] ) ------------
__global__ __launch_bounds__(256, 2)
void gemm2_kernel(const float* __restrict__ W2,
                  const float* __restrict__ b2,
                  float* __restrict__ out) {
    __shared__ float As[BK][BM + 4];
    __shared__ float Bs[BK][BN + 4];

    int e  = blockIdx.z;
    int loadE = g_load[e];
    int m0 = blockIdx.y * BM;
    int n0 = blockIdx.x * BN;
    if (m0 >= loadE) return;
    int tid = threadIdx.x;
    int tx = tid & 15, ty = tid >> 4;

    const float* A = g_H + (size_t)e * CAP * DIM;
    const float* W = W2 + (size_t)e * DIM * DIM;
    int sr = tid >> 1;
    int sk = (tid & 1) << 3;
    const float* pa = A + (size_t)(m0 + sr) * DIM + sk;
    const float* pb = W + (size_t)(n0 + sr) * DIM + sk;

    float acc[8][8];
#pragma unroll
    for (int i = 0; i < 8; i++)
#pragma unroll
        for (int j = 0; j < 8; j++) acc[i][j] = 0.f;

#pragma unroll 1
    for (int k0 = 0; k0 < DIM; k0 += BK) {
        float4 av0 = *(const float4*)(pa + k0);
        float4 av1 = *(const float4*)(pa + k0 + 4);
        float4 bv0 = *(const float4*)(pb + k0);
        float4 bv1 = *(const float4*)(pb + k0 + 4);
        __syncthreads();
        As[sk + 0][sr] = av0.x; As[sk + 1][sr] = av0.y;
        As[sk + 2][sr] = av0.z; As[sk + 3][sr] = av0.w;
        As[sk + 4][sr] = av1.x; As[sk + 5][sr] = av1.y;
        As[sk + 6][sr] = av1.z; As[sk + 7][sr] = av1.w;
        Bs[sk + 0][sr] = bv0.x; Bs[sk + 1][sr] = bv0.y;
        Bs[sk + 2][sr] = bv0.z; Bs[sk + 3][sr] = bv0.w;
        Bs[sk + 4][sr] = bv1.x; Bs[sk + 5][sr] = bv1.y;
        Bs[sk + 6][sr] = bv1.z; Bs[sk + 7][sr] = bv1.w;
        __syncthreads();
#pragma unroll
        for (int kk = 0; kk < BK; kk++) {
            float a[8], b[8];
            *(float4*)(a)     = *(const float4*)&As[kk][ty * 4];
            *(float4*)(a + 4) = *(const float4*)&As[kk][64 + ty * 4];
            *(float4*)(b)     = *(const float4*)&Bs[kk][tx * 4];
            *(float4*)(b + 4) = *(const float4*)&Bs[kk][64 + tx * 4];
#pragma unroll
            for (int i = 0; i < 8; i++)
#pragma unroll
                for (int j = 0; j < 8; j++) acc[i][j] += a[i] * b[j];
        }
    }

    float b2v[8];
#pragma unroll
    for (int j = 0; j < 8; j++) {
        int c = (j < 4) ? tx * 4 + j : 64 + tx * 4 + j - 4;
        b2v[j] = b2[e * DIM + n0 + c];
    }
#pragma unroll
    for (int i = 0; i < 8; i++) {
        int m = m0 + ((i < 4) ? ty * 4 + i : 64 + ty * 4 + i - 4);
        if (m < loadE) {
            int   tok = g_row_token[e * CAP + m];
            float gt  = g_row_gate[e * CAP + m];
            float* op = out + (size_t)tok * DIM + n0;
#pragma unroll
            for (int j = 0; j < 8; j++) {
                int c = (j < 4) ? tx * 4 + j : 64 + tx * 4 + j - 4;
                atomicAdd(&op[c], (acc[i][j] + b2v[j]) * gt);
            }
        }
    }
}

// ---------------- load-balancing stats ------------------------------------
__global__ void stats_kernel(float* __restrict__ out) {
    if (threadIdx.x == 0) {
        float l[NE], s = 0.f;
#pragma unroll
        for (int e = 0; e < NE; e++) { l[e] = (float)g_load[e]; s += l[e]; }
        float inv = 1.f / (s + 1e-8f);
        float loss = 0.f;
#pragma unroll
        for (int e = 0; e < NE; e++) {
            float d = l[e] * inv;
            out[(size_t)NTOK * DIM + 1 + e] = d;
            loss -= d * logf(d + 1e-8f);
        }
        out[(size_t)NTOK * DIM] = loss;
    }
}

// ---------------- launch ---------------------------------------------------
extern "C" void kernel_launch(void* const* d_in, const int* in_sizes, int n_in,
                              void* d_out, int out_size) {
    const float* x  = (const float*)d_in[0];
    const float* Wr = (const float*)d_in[1];
    const float* br = (const float*)d_in[2];
    const float* W1 = (const float*)d_in[3];
    const float* b1 = (const float*)d_in[4];
    const float* W2 = (const float*)d_in[5];
    const float* b2 = (const float*)d_in[6];
    float* out = (float*)d_out;

    cudaMemsetAsync(out, 0, (size_t)NTOK * DIM * sizeof(float), 0);
    router_kernel<<<NTOK / 8, 256>>>(x, Wr, br);
    scan_kernel<<<NE, 1024>>>();
    dim3 grid(DIM / BN, CAP / BM, NE);
    gemm1_kernel<<<grid, 256>>>(x, W1, b1);
    gemm2_kernel<<<grid, 256>>>(W2, b2, out);
    stats_kernel<<<1, 32>>>(out);
}

// round 3
// speedup vs baseline: 1.8357x; 1.8357x over previous
#include <cuda_runtime.h>
#include <cstdint>
#include <math.h>

#define NTOK 16384
#define DIM  1024
#define NE   8
#define CAP  2560          // int(1.25 * 16384 / 8)
#define BK   32
#define NCH  (DIM / BK)
#define PITCH 80           // bytes per SMEM tile row (32 bf16 = 64B + 16B pad)

// ---------------- device scratch (no allocation allowed) -------------------
__device__ int   g_top[NTOK * 2];
__device__ float g_gate[NTOK * 2];
__device__ int   g_slot[NTOK * 2];        // slot within expert, -1 if dropped
__device__ int   g_row_token[NE * CAP];
__device__ int   g_load[NE];
__device__ float g_H[(size_t)NE * CAP * DIM];   // hidden activations (84 MB)
__device__ float g_O[(size_t)NE * CAP * DIM];   // expert outputs + b2 (84 MB)

// ---------------- helpers ---------------------------------------------------
__device__ __forceinline__ uint32_t smem_u32(const void* p) {
    uint32_t a;
    asm("{ .reg .u64 t; cvta.to.shared.u64 t, %1; cvt.u32.u64 %0, t; }"
        : "=r"(a) : "l"(p));
    return a;
}

// split 8 fp32 -> 8 bf16 hi (uint4) + 8 bf16 lo (uint4)
__device__ __forceinline__ void split8(const float4 f0, const float4 f1,
                                       uint4& hi, uint4& lo) {
    const float f[8] = {f0.x, f0.y, f0.z, f0.w, f1.x, f1.y, f1.z, f1.w};
    uint32_t h[4], l[4];
#pragma unroll
    for (int i = 0; i < 4; i++) {
        float a = f[2 * i], b = f[2 * i + 1];
        uint32_t hp;
        asm("cvt.rn.bf16x2.f32 %0, %1, %2;" : "=r"(hp) : "f"(b), "f"(a));
        float ra = a - __uint_as_float(hp << 16);
        float rb = b - __uint_as_float(hp & 0xFFFF0000u);
        uint32_t lp;
        asm("cvt.rn.bf16x2.f32 %0, %1, %2;" : "=r"(lp) : "f"(rb), "f"(ra));
        h[i] = hp; l[i] = lp;
    }
    hi = make_uint4(h[0], h[1], h[2], h[3]);
    lo = make_uint4(l[0], l[1], l[2], l[3]);
}

__device__ __forceinline__ void ldsm4(uint32_t* r, uint32_t addr) {
    asm volatile("ldmatrix.sync.aligned.m8n8.x4.shared.b16 {%0,%1,%2,%3}, [%4];"
                 : "=r"(r[0]), "=r"(r[1]), "=r"(r[2]), "=r"(r[3]) : "r"(addr));
}
__device__ __forceinline__ void ldsm2(uint32_t* r, uint32_t addr) {
    asm volatile("ldmatrix.sync.aligned.m8n8.x2.shared.b16 {%0,%1}, [%2];"
                 : "=r"(r[0]), "=r"(r[1]) : "r"(addr));
}
__device__ __forceinline__ void mma_bf16(float* d, const uint32_t* a,
                                         const uint32_t* b) {
    asm volatile(
        "mma.sync.aligned.m16n8k16.row.col.f32.bf16.bf16.f32 "
        "{%0,%1,%2,%3}, {%4,%5,%6,%7}, {%8,%9}, {%0,%1,%2,%3};"
        : "+f"(d[0]), "+f"(d[1]), "+f"(d[2]), "+f"(d[3])
        : "r"(a[0]), "r"(a[1]), "r"(a[2]), "r"(a[3]), "r"(b[0]), "r"(b[1]));
}

// ---------------- tensor-core (HMMA) GEMM, both layers ---------------------
// C[128 x 128] = A[128 x 1024] @ W[e][128 x 1024]^T  (+bias, relu for G1)
// 3-term bf16 split: Ah*Bh + Ah*Bl + Al*Bh, fp32 accumulate.
template <bool G2>
__global__ void __launch_bounds__(256)
moe_gemm(const float* __restrict__ Asrc, const float* __restrict__ Wsrc,
         const float* __restrict__ bias) {
    __shared__ __align__(16) unsigned char sm[512 + 4 * 128 * PITCH];
    int* rows = (int*)sm;
    unsigned char* Ah = sm + 512;
    unsigned char* Al = Ah + 128 * PITCH;
    unsigned char* Bh = Al + 128 * PITCH;
    unsigned char* Bl = Bh + 128 * PITCH;

    const int e = blockIdx.z;
    const int loadE = g_load[e];
    const int m0 = blockIdx.y * 128;
    if (m0 >= loadE) return;
    const int n0 = blockIdx.x * 128;
    const int tid = threadIdx.x;
    const int lane = tid & 31, wid = tid >> 5;
    const int wm = wid >> 2, wn = wid & 3;     // warp tile: 64 rows x 32 cols

    if (!G2 && tid < 128) {
        int m = m0 + tid;
        rows[tid] = g_row_token[e * CAP + (m < loadE ? m : loadE - 1)];
    }
    __syncthreads();

    // global load assignment: thread -> (row r, 16-float column group)
    const int r = tid >> 1;
    const int cofs = (tid & 1) * 16;
    const float* pa = G2 ? (g_H + ((size_t)e * CAP + m0 + r) * DIM + cofs)
                         : (Asrc + (size_t)rows[r] * DIM + cofs);
    const float* pb = Wsrc + ((size_t)e * DIM + n0 + r) * DIM + cofs;
    const uint32_t sa = (uint32_t)r * PITCH + (uint32_t)(tid & 1) * 32;

    const uint32_t aAh = smem_u32(Ah), aAl = smem_u32(Al);
    const uint32_t aBh = smem_u32(Bh), aBl = smem_u32(Bl);
    // ldmatrix per-lane row offsets
    const uint32_t arow = (uint32_t)(wm * 64 + (lane & 15)) * PITCH + (lane >> 4) * 16;
    const uint32_t brow = (uint32_t)(wn * 32 + (lane & 7)) * PITCH + ((lane >> 3) & 1) * 16;

    float4 fa[4], fb[4];
    float acc[4][4][4];
#pragma unroll
    for (int i = 0; i < 4; i++)
#pragma unroll
        for (int j = 0; j < 4; j++)
#pragma unroll
            for (int k = 0; k < 4; k++) acc[i][j][k] = 0.f;

    auto ldglobal = [&](int c) {
        const float4* qa = (const float4*)(pa + c * BK);
        const float4* qb = (const float4*)(pb + c * BK);
#pragma unroll
        for (int i = 0; i < 4; i++) { fa[i] = __ldg(qa + i); fb[i] = __ldg(qb + i); }
    };
    auto stchunk = [&]() {
        uint4 h, l;
        split8(fa[0], fa[1], h, l);
        *(uint4*)(Ah + sa) = h;      *(uint4*)(Al + sa) = l;
        split8(fa[2], fa[3], h, l);
        *(uint4*)(Ah + sa + 16) = h; *(uint4*)(Al + sa + 16) = l;
        split8(fb[0], fb[1], h, l);
        *(uint4*)(Bh + sa) = h;      *(uint4*)(Bl + sa) = l;
        split8(fb[2], fb[3], h, l);
        *(uint4*)(Bh + sa + 16) = h; *(uint4*)(Bl + sa + 16) = l;
    };
    auto compute = [&]() {
#pragma unroll
        for (int t = 0; t < 3; t++) {
            const uint32_t Ab = (t == 2) ? aAl : aAh;
            const uint32_t Bb = (t == 1) ? aBl : aBh;
#pragma unroll
            for (int s = 0; s < 2; s++) {
                uint32_t af[4][4], bf[4][2];
#pragma unroll
                for (int ms = 0; ms < 4; ms++)
                    ldsm4(af[ms], Ab + arow + ms * (16 * PITCH) + s * 32);
#pragma unroll
                for (int ns = 0; ns < 4; ns++)
                    ldsm2(bf[ns], Bb + brow + ns * (8 * PITCH) + s * 32);
#pragma unroll
                for (int ms = 0; ms < 4; ms++)
#pragma unroll
                    for (int ns = 0; ns < 4; ns++)
                        mma_bf16(acc[ms][ns], af[ms], bf[ns]);
            }
        }
    };

    ldglobal(0);
    stchunk();
    __syncthreads();
#pragma unroll 1
    for (int c = 0; c < NCH; c++) {
        if (c + 1 < NCH) ldglobal(c + 1);   // prefetch overlaps HMMA below
        compute();
        __syncthreads();
        if (c + 1 < NCH) { stchunk(); __syncthreads(); }
    }

    // epilogue
    const float* bE = bias + e * DIM;
    float* dst = (G2 ? g_O : g_H);
#pragma unroll
    for (int ms = 0; ms < 4; ms++) {
        const int row = m0 + wm * 64 + ms * 16 + (lane >> 2);
#pragma unroll
        for (int ns = 0; ns < 4; ns++) {
            const int col = n0 + wn * 32 + ns * 8 + 2 * (lane & 3);
            const float2 bv = *(const float2*)(bE + col);
            float2 v0, v1;
            v0.x = acc[ms][ns][0] + bv.x; v0.y = acc[ms][ns][1] + bv.y;
            v1.x = acc[ms][ns][2] + bv.x; v1.y = acc[ms][ns][3] + bv.y;
            if (!G2) {
                v0.x = v0.x > 0.f ? v0.x : 0.f; v0.y = v0.y > 0.f ? v0.y : 0.f;
                v1.x = v1.x > 0.f ? v1.x : 0.f; v1.y = v1.y > 0.f ? v1.y : 0.f;
            }
            float* p0 = dst + ((size_t)e * CAP + row) * DIM + col;
            *(float2*)p0 = v0;
            *(float2*)(p0 + 8 * DIM) = v1;
        }
    }
}

// ---------------- router ---------------------------------------------------
__global__ void router_kernel(const float* __restrict__ x,
                              const float* __restrict__ Wr,
                              const float* __restrict__ br) {
    int token = (blockIdx.x * blockDim.x + threadIdx.x) >> 5;
    int lane  = threadIdx.x & 31;
    if (token >= NTOK) return;
    const float* xr = x + (size_t)token * DIM;
    float acc[NE];
#pragma unroll
    for (int e = 0; e < NE; e++) acc[e] = 0.f;
    for (int d = lane; d < DIM; d += 32) {
        float xv = xr[d];
#pragma unroll
        for (int e = 0; e < NE; e++) acc[e] += xv * Wr[e * DIM + d];
    }
#pragma unroll
    for (int e = 0; e < NE; e++)
#pragma unroll
        for (int o = 16; o; o >>= 1)
            acc[e] += __shfl_xor_sync(0xffffffffu, acc[e], o);
    if (lane == 0) {
        float l[NE];
#pragma unroll
        for (int e = 0; e < NE; e++) l[e] = acc[e] + br[e];
        float v1 = -3.4e38f; int i1 = 0;
#pragma unroll
        for (int e = 0; e < NE; e++) if (l[e] > v1) { v1 = l[e]; i1 = e; }
        float v2 = -3.4e38f; int i2 = 0;
#pragma unroll
        for (int e = 0; e < NE; e++) if (e != i1 && l[e] > v2) { v2 = l[e]; i2 = e; }
        float ex = expf(v2 - v1);
        float inv = 1.f / (1.f + ex);
        g_top[2 * token]      = i1;
        g_top[2 * token + 1]  = i2;
        g_gate[2 * token]     = inv;
        g_gate[2 * token + 1] = ex * inv;
    }
}

// ---------------- dispatch scan --------------------------------------------
__global__ void scan_kernel() {
    int e = blockIdx.x;
    __shared__ int wsum[32];
    __shared__ int total_s;
    int lane = threadIdx.x & 31;
    int wid  = threadIdx.x >> 5;
    int running = 0;
    for (int base = 0; base < NTOK; base += 1024) {
        int n = base + threadIdx.x;
        int k = -1;
        int t0 = g_top[2 * n], t1 = g_top[2 * n + 1];
        if (t0 == e) k = 0; else if (t1 == e) k = 1;
        unsigned b = __ballot_sync(0xffffffffu, k >= 0);
        int pw = __popc(b & ((1u << lane) - 1u));
        if (lane == 0) wsum[wid] = __popc(b);
        __syncthreads();
        if (wid == 0) {
            int v = wsum[lane];
            int s = v;
#pragma unroll
            for (int o = 1; o < 32; o <<= 1) {
                int u = __shfl_up_sync(0xffffffffu, s, o);
                if (lane >= o) s += u;
            }
            wsum[lane] = s - v;
            if (lane == 31) total_s = s;
        }
        __syncthreads();
        if (k >= 0) {
            int pos = running + wsum[wid] + pw;
            if (pos < CAP) {
                g_row_token[e * CAP + pos] = n;
                g_slot[2 * n + k] = pos;
            } else {
                g_slot[2 * n + k] = -1;
            }
        }
        running += total_s;
        __syncthreads();
    }
    if (threadIdx.x == 0) g_load[e] = running < CAP ? running : CAP;
}

// ---------------- combine: out[t] = sum_k gate * O[e_k, slot_k] ------------
__global__ void combine_kernel(float* __restrict__ out) {
    int t = blockIdx.x * 8 + (threadIdx.x >> 5);
    int lane = threadIdx.x & 31;
    float4 acc[8];
#pragma unroll
    for (int i = 0; i < 8; i++) acc[i] = make_float4(0.f, 0.f, 0.f, 0.f);
#pragma unroll
    for (int k = 0; k < 2; k++) {
        int s = g_slot[2 * t + k];
        if (s >= 0) {
            int e = g_top[2 * t + k];
            float g = g_gate[2 * t + k];
            const float4* p = (const float4*)(g_O + ((size_t)e * CAP + s) * DIM);
#pragma unroll
            for (int i = 0; i < 8; i++) {
                float4 v = __ldg(p + lane + i * 32);
                acc[i].x += g * v.x; acc[i].y += g * v.y;
                acc[i].z += g * v.z; acc[i].w += g * v.w;
            }
        }
    }
    float4* o = (float4*)(out + (size_t)t * DIM);
#pragma unroll
    for (int i = 0; i < 8; i++) o[lane + i * 32] = acc[i];
}

// ---------------- stats -----------------------------------------------------
__global__ void stats_kernel(float* __restrict__ out) {
    if (threadIdx.x == 0) {
        float l[NE], s = 0.f;
#pragma unroll
        for (int e = 0; e < NE; e++) { l[e] = (float)g_load[e]; s += l[e]; }
        float inv = 1.f / (s + 1e-8f);
        float loss = 0.f;
#pragma unroll
        for (int e = 0; e < NE; e++) {
            float d = l[e] * inv;
            out[(size_t)NTOK * DIM + 1 + e] = d;
            loss -= d * logf(d + 1e-8f);
        }
        out[(size_t)NTOK * DIM] = loss;
    }
}

// ---------------- launch ----------------------------------------------------
extern "C" void kernel_launch(void* const* d_in, const int* in_sizes, int n_in,
                              void* d_out, int out_size) {
    const float* x  = (const float*)d_in[0];
    const float* Wr = (const float*)d_in[1];
    const float* br = (const float*)d_in[2];
    const float* W1 = (const float*)d_in[3];
    const float* b1 = (const float*)d_in[4];
    const float* W2 = (const float*)d_in[5];
    const float* b2 = (const float*)d_in[6];
    float* out = (float*)d_out;

    router_kernel<<<NTOK / 8, 256>>>(x, Wr, br);
    scan_kernel<<<NE, 1024>>>();
    dim3 grid(DIM / 128, CAP / 128, NE);
    moe_gemm<false><<<grid, 256>>>(x, W1, b1);
    moe_gemm<true><<<grid, 256>>>(x, W2, b2);
    combine_kernel<<<NTOK / 8, 256>>>(out);
    stats_kernel<<<1, 32>>>(out);
}